// round 2
// baseline (speedup 1.0000x reference)
#include <cuda_runtime.h>
#include <cuda_bf16.h>

// One-pole IIR filter, time-chunked with exponential-decay halo warm-up.
//   out[t]  = b0*x[t] + s[t]
//   s[t+1]  = b1*x[t] + a1c*out[t] = (b1 + a1c*b0)*x[t] + a1c*s[t]
// Each (chunk, column) thread warms up over W halo rows starting from s=0
// (valid because |a1c|^W <= 1e-12), then emits its L output rows. Chunk 0
// (or the exact-fallback case W==t0) starts from the true initial state.

__global__ void __launch_bounds__(256) onepole_chunked_kernel(
    const float* __restrict__ x,
    const float* __restrict__ state,
    const float* __restrict__ b0p,
    const float* __restrict__ b1p,
    const float* __restrict__ a1p,
    float* __restrict__ out,
    int T, int B, int L, int write_final)
{
    int col = blockIdx.x * blockDim.x + threadIdx.x;
    if (col >= B) return;
    int chunk = blockIdx.y;
    int t0 = chunk * L;
    if (t0 >= T) return;
    int t1 = t0 + L; if (t1 > T) t1 = T;

    float b0 = b0p[0];
    float b1 = b1p[0];
    float a1 = a1p[0];
    a1 = fminf(1.0f, fmaxf(-1.0f, a1));       // reference clamps a1 to [-1,1]
    const float aa = fabsf(a1);
    const float cc = fmaf(a1, b0, b1);        // combined state coefficient

    // Warm-up length: smallest W with |a1|^W <= 1e-12 (runtime-adaptive).
    int W;
    if (aa < 1e-30f) {
        W = 0;                                 // state contribution vanishes in 1 step
    } else if (aa > 0.999f) {
        W = t0;                                // near-|1|: no decay -> exact full warmup
    } else {
        W = (int)ceilf(-27.7f / logf(aa));     // ln(1e-12) = -27.63
        if (W > t0) W = t0;
    }

    const int tw = t0 - W;
    // tw == 0 means warm-up spans from t=0 (chunk 0 or exact fallback):
    // start from the true initial state so the result is exact.
    float s = (tw == 0) ? state[col] : 0.0f;

    const float* __restrict__ xp = x + (size_t)tw * (size_t)B + col;

    // Halo warm-up: state recurrence only, no stores.
    #pragma unroll 4
    for (int t = tw; t < t0; ++t) {
        float xv = *xp; xp += B;
        s = fmaf(a1, s, cc * xv);
    }

    // Main chunk: emit outputs. Loads are independent of the s-chain, so the
    // unrolled loop lets ptxas batch LDGs well ahead of the dependent FMAs.
    float* __restrict__ yp = out + (size_t)t0 * (size_t)B + col;
    #pragma unroll 8
    for (int t = t0; t < t1; ++t) {
        float xv = *xp; xp += B;
        float o = fmaf(b0, xv, s);
        *yp = o; yp += B;
        s = fmaf(a1, s, cc * xv);
    }

    // Last chunk owns the exact final state.
    if (write_final && t1 == T) {
        out[(size_t)T * (size_t)B + col] = s;
    }
}

extern "C" void kernel_launch(void* const* d_in, const int* in_sizes, int n_in,
                              void* d_out, int out_size)
{
    const float* x     = (const float*)d_in[0];
    const float* state = (const float*)d_in[1];
    const float* b0    = (const float*)d_in[2];
    const float* b1    = (const float*)d_in[3];
    const float* a1    = (const float*)d_in[4];
    float* out = (float*)d_out;

    const int B = in_sizes[1];            // state has B elements
    const int T = in_sizes[0] / B;        // x is [T, B]

    const int CHUNKS = 32;
    const int L = (T + CHUNKS - 1) / CHUNKS;
    const int nchunks = (T + L - 1) / L;
    const int write_final = (out_size >= T * B + B) ? 1 : 0;

    dim3 block(256);
    dim3 grid((B + 255) / 256, nchunks);
    onepole_chunked_kernel<<<grid, block>>>(x, state, b0, b1, a1, out,
                                            T, B, L, write_final);
}